// round 15
// baseline (speedup 1.0000x reference)
#include <cuda_runtime.h>
#include <cuda_bf16.h>
#include <cstdint>
#include <math.h>

constexpr int B = 4, S = 2048, D = 1024, H = 16, HD = 64;
constexpr int NR = B * S;  // 8192 rows

// ---------------- scratch (static device globals; no allocation) -------------
__device__ __nv_bfloat16 g_Xb[(size_t)NR * D];      // x bf16
__device__ __nv_bfloat16 g_Wb[(size_t)4 * D * D];   // Wq,Wk,Wv,Wo bf16
__device__ __nv_bfloat16 g_Qb[(size_t)NR * D];      // pre-scaled by 0.125*log2e
__device__ __nv_bfloat16 g_Kb[(size_t)NR * D];
__device__ __nv_bfloat16 g_Vb[(size_t)NR * D];
__device__ __nv_bfloat16 g_Cb[(size_t)NR * D];      // attention out bf16
__device__ float         g_Y[(size_t)NR * D];

// ======================= helpers ============================================
__device__ __forceinline__ uint32_t smem_u32(const void* p) {
    uint32_t a;
    asm("{ .reg .u64 t; cvta.to.shared.u64 t, %1; cvt.u32.u64 %0, t; }"
        : "=r"(a) : "l"(p));
    return a;
}
__device__ __forceinline__ void ldsm4(uint32_t& r0, uint32_t& r1, uint32_t& r2,
                                      uint32_t& r3, uint32_t addr) {
    asm volatile("ldmatrix.sync.aligned.m8n8.x4.shared.b16 {%0,%1,%2,%3}, [%4];"
                 : "=r"(r0), "=r"(r1), "=r"(r2), "=r"(r3) : "r"(addr));
}
__device__ __forceinline__ void ldsm4t(uint32_t& r0, uint32_t& r1, uint32_t& r2,
                                       uint32_t& r3, uint32_t addr) {
    asm volatile("ldmatrix.sync.aligned.m8n8.x4.trans.shared.b16 {%0,%1,%2,%3}, [%4];"
                 : "=r"(r0), "=r"(r1), "=r"(r2), "=r"(r3) : "r"(addr));
}
__device__ __forceinline__ void mma16(float (&c)[4], const uint32_t (&a)[4],
                                      uint32_t b0, uint32_t b1) {
    asm volatile(
        "mma.sync.aligned.m16n8k16.row.col.f32.bf16.bf16.f32 "
        "{%0,%1,%2,%3}, {%4,%5,%6,%7}, {%8,%9}, {%0,%1,%2,%3};"
        : "+f"(c[0]), "+f"(c[1]), "+f"(c[2]), "+f"(c[3])
        : "r"(a[0]), "r"(a[1]), "r"(a[2]), "r"(a[3]), "r"(b0), "r"(b1));
}
__device__ __forceinline__ void cp_async16(uint32_t s, const void* g) {
    asm volatile("cp.async.cg.shared.global [%0], [%1], 16;" :: "r"(s), "l"(g));
}
__device__ __forceinline__ void cp_commit() {
    asm volatile("cp.async.commit_group;" ::: "memory");
}
template <int N>
__device__ __forceinline__ void cp_wait() {
    asm volatile("cp.async.wait_group %0;" :: "n"(N) : "memory");
}
__device__ __forceinline__ uint32_t packbf(float x, float y) {
    __nv_bfloat162 p = __floats2bfloat162_rn(x, y);
    return *(uint32_t*)&p;
}
__device__ __forceinline__ uint32_t hmax2u(uint32_t a, uint32_t b) {
    __nv_bfloat162 x = *(__nv_bfloat162*)&a;
    __nv_bfloat162 y = *(__nv_bfloat162*)&b;
    __nv_bfloat162 r = __hmax2(x, y);
    return *(uint32_t*)&r;
}

// ======================= fp32 -> bf16 prep ===================================
__global__ __launch_bounds__(256) void cvt_bf16(const float* __restrict__ in,
                                                __nv_bfloat16* __restrict__ out,
                                                int n4)
{
    const int i = (blockIdx.x * 256 + threadIdx.x) * 4;
    if (i < n4 * 4) {
        float4 v = *(const float4*)(in + i);
        uint2 u;
        u.x = packbf(v.x, v.y);
        u.y = packbf(v.z, v.w);
        *(uint2*)(out + i) = u;
    }
}

struct WPtrs { const float* w[4]; };

__global__ __launch_bounds__(256) void cvt_w4(WPtrs ws,
                                              __nv_bfloat16* __restrict__ out)
{
    const int i = (blockIdx.x * 256 + threadIdx.x) * 4;
    const float* in = ws.w[blockIdx.y];
    __nv_bfloat16* o = out + (size_t)blockIdx.y * D * D;
    float4 v = *(const float4*)(in + i);
    uint2 u;
    u.x = packbf(v.x, v.y);
    u.y = packbf(v.z, v.w);
    *(uint2*)(o + i) = u;
}

// ======================= bf16 mma GEMM core (BK=32, 4 CTAs/SM) ==============
constexpr int GST = 40;                 // smem row stride (bf16): 32 + 8 pad
constexpr int G_STAGE = 256 * GST;      // bf16 elems per stage (10240)
constexpr int GEMM_SMEM = 2 * G_STAGE * 2;  // 40960 B -> 4 CTAs/SM

struct QKVOut {
    __nv_bfloat16* out[3];
    const float* bias[3];
    float oscale[3];
};

template <typename AccFn>
__device__ __forceinline__ void gemm_body(
    const __nv_bfloat16* __restrict__ A, const __nv_bfloat16* __restrict__ W,
    int n0, int m0, __nv_bfloat16* gsm, AccFn&& emit)
{
    const int tid = threadIdx.x;
    const int lane = tid & 31, wid = tid >> 5;   // 4 warps
    const int wr = wid >> 1, wc = wid & 1;        // 2x2 warp grid, 64x64 each
    const int lrow = lane & 15;
    const int lcol8 = (lane >> 4) * 8;
    const uint32_t sbase = smem_u32(gsm);

    float acc[4][8][4];
#pragma unroll
    for (int mt = 0; mt < 4; mt++)
#pragma unroll
        for (int nt = 0; nt < 8; nt++)
#pragma unroll
            for (int q = 0; q < 4; q++) acc[mt][nt][q] = 0.f;

    // BK=32: each chunk is 256 rows x 32 bf16. 8 cp.async16 per thread? no:
    // 256 rows x 32 cols = 8192 elems = 512 x 16B ops -> 4 per thread (128 thr).
    auto issue_chunk = [&](int c) {
        const int k0 = c * 32;
        const uint32_t stb = sbase + (c & 1) * G_STAGE * 2;
#pragma unroll
        for (int i = 0; i < 8; i++) {
            const int idx = tid + i * 128;
            const int t = idx & 511;
            const int row = t >> 2, c8 = (t & 3) * 8;
            const __nv_bfloat16* g =
                (idx < 512 ? A + (size_t)(n0 + row) * D
                           : W + (size_t)(m0 + row) * D) + k0 + c8;
            const int srow = row + (idx < 512 ? 0 : 128);
            cp_async16(stb + (srow * GST + c8) * 2, g);
        }
        cp_commit();
    };

    issue_chunk(0);
    for (int c = 0; c < 32; c++) {
        if (c < 31) issue_chunk(c + 1);
        if (c < 31) cp_wait<1>(); else cp_wait<0>();
        __syncthreads();

        const uint32_t stb = sbase + (c & 1) * G_STAGE * 2;
#pragma unroll
        for (int k = 0; k < 2; k++) {
            uint32_t a[4][4];
            uint32_t bfr[8][2];
#pragma unroll
            for (int mt = 0; mt < 4; mt++) {
                const uint32_t addr =
                    stb + ((wr * 64 + mt * 16 + lrow) * GST + k * 16 + lcol8) * 2;
                ldsm4(a[mt][0], a[mt][1], a[mt][2], a[mt][3], addr);
            }
#pragma unroll
            for (int np = 0; np < 4; np++) {
                const uint32_t addr =
                    stb + ((128 + wc * 64 + np * 16 + lrow) * GST + k * 16 + lcol8) * 2;
                uint32_t b0, b1, b2, b3;
                ldsm4(b0, b1, b2, b3, addr);
                bfr[np * 2 + 0][0] = b0; bfr[np * 2 + 1][0] = b1;
                bfr[np * 2 + 0][1] = b2; bfr[np * 2 + 1][1] = b3;
            }
#pragma unroll
            for (int mt = 0; mt < 4; mt++)
#pragma unroll
                for (int nt = 0; nt < 8; nt++)
                    mma16(acc[mt][nt], a[mt], bfr[nt][0], bfr[nt][1]);
        }
        __syncthreads();
    }

    const int g = lane >> 2, cc = lane & 3;
#pragma unroll
    for (int mt = 0; mt < 4; mt++)
#pragma unroll
        for (int hf = 0; hf < 2; hf++) {
            const int row = n0 + wr * 64 + mt * 16 + g + hf * 8;
#pragma unroll
            for (int nt = 0; nt < 8; nt++) {
                const int col = m0 + wc * 64 + nt * 8 + cc * 2;
                emit(row, col, acc[mt][nt][hf * 2 + 0], acc[mt][nt][hf * 2 + 1]);
            }
        }
}

// Fused QKV projection: grid.x in [0,24): sel = x>>3, m-block = x&7.
__global__ __launch_bounds__(128, 4) void qkv_gemm(
    const __nv_bfloat16* __restrict__ A, const __nv_bfloat16* __restrict__ Wall,
    QKVOut io)
{
    extern __shared__ __nv_bfloat16 gsm[];
    const int sel = blockIdx.x >> 3;
    const int m0 = (blockIdx.x & 7) * 128;
    const int n0 = blockIdx.y * 128;
    const __nv_bfloat16* W = Wall + (size_t)sel * D * D;
    __nv_bfloat16* out = io.out[sel];
    const float* bias = io.bias[sel];
    const float os = io.oscale[sel];

    gemm_body(A, W, n0, m0, gsm,
              [&](int row, int col, float vx, float vy) {
                  float2 bv = *(const float2*)(bias + col);
                  *(uint32_t*)(out + (size_t)row * D + col) =
                      packbf((vx + bv.x) * os, (vy + bv.y) * os);
              });
}

// Output projection with residual, fp32 out.
__global__ __launch_bounds__(128, 4) void out_gemm(
    const __nv_bfloat16* __restrict__ A, const __nv_bfloat16* __restrict__ W,
    const float* __restrict__ bias, const float* __restrict__ R,
    float* __restrict__ C)
{
    extern __shared__ __nv_bfloat16 gsm[];
    const int m0 = blockIdx.x * 128;
    const int n0 = blockIdx.y * 128;

    gemm_body(A, W, n0, m0, gsm,
              [&](int row, int col, float vx, float vy) {
                  float2 bv = *(const float2*)(bias + col);
                  float2 rv = *(const float2*)(R + (size_t)row * D + col);
                  float2 o;
                  o.x = vx + bv.x + rv.x;
                  o.y = vy + bv.y + rv.y;
                  *(float2*)(C + (size_t)row * D + col) = o;
              });
}

// ======================= bf16 mma flash attention ===========================
// Block: 128 q rows, 8 warps x 16 rows, 256 threads, 2 CTAs/SM. (R14 config)
constexpr int AST = 72;
constexpr int AQ_E = 0;
constexpr int AK_E = 128 * AST;
constexpr int AV_E = AK_E + 3 * 64 * AST;
constexpr int AEND_E = AV_E + 3 * 64 * AST;
constexpr int AM_BYTE = AEND_E * 2;
constexpr int ATT_SMEM = AM_BYTE + 3 * 64 * 4;  // ~74.5 KB
constexpr int KSTG = 64 * AST;
constexpr uint32_t SROT = KSTG * 2;

__global__ __launch_bounds__(256, 2) void attn_mma(
    const __nv_bfloat16* __restrict__ Q, const __nv_bfloat16* __restrict__ K,
    const __nv_bfloat16* __restrict__ V, const int* __restrict__ mask,
    __nv_bfloat16* __restrict__ O)
{
    extern __shared__ __nv_bfloat16 smb[];
    int* ms = (int*)((char*)smb + AM_BYTE);
    const int tid = threadIdx.x, lane = tid & 31, wid = tid >> 5;
    const int b = blockIdx.z, h = blockIdx.y, q0 = blockIdx.x * 128;
    const uint32_t sb = smem_u32(smb);
    const int lrow = lane & 15;
    const int lcol8 = (lane >> 4) * 8;
    const int lrow_t = (lane & 7) + ((lane >> 4) << 3);
    const int dsel = ((lane >> 3) & 1) * 8;
    const int g = lane >> 2, cc = lane & 3;
    const int qb = wid * 16;
    const float mneg2 = -1.44269504e9f;   // -1e9 * log2(e)

    // Q tile (128 x 64 bf16) via cp.async — first commit group
#pragma unroll
    for (int i = 0; i < 4; i++) {
        const int idx = tid + i * 256;
        const int row = idx >> 3, c8 = (idx & 7) * 8;
        cp_async16(sb + (AQ_E + row * AST + c8) * 2,
                   Q + (size_t)(b * S + q0 + row) * D + h * HD + c8);
    }
    cp_commit();

    auto issueKV = [&](int k0, int stage) {
#pragma unroll
        for (int j = 0; j < 2; j++) {
            const int idx = tid + j * 256;
            const int row = idx >> 3, c8 = (idx & 7) * 8;
            cp_async16(sb + ((AK_E + stage * KSTG) + row * AST + c8) * 2,
                       K + (size_t)(b * S + k0 + row) * D + h * HD + c8);
            cp_async16(sb + ((AV_E + stage * KSTG) + row * AST + c8) * 2,
                       V + (size_t)(b * S + k0 + row) * D + h * HD + c8);
        }
        if (tid < 16)
            cp_async16(sb + AM_BYTE + stage * 256 + tid * 16,
                       mask + b * S + k0 + tid * 4);
        cp_commit();
    };

    issueKV(0, 0);
    issueKV(64, 1);

    // Hoist Q fragments
    cp_wait<2>();
    __syncthreads();
    uint32_t aq[4][4];
#pragma unroll
    for (int k = 0; k < 4; k++) {
        const uint32_t addr =
            sb + ((AQ_E + (qb + lrow) * AST) + k * 16 + lcol8) * 2;
        ldsm4(aq[k][0], aq[k][1], aq[k][2], aq[k][3], addr);
    }

    float ob[8][4];
#pragma unroll
    for (int nt = 0; nt < 8; nt++)
#pragma unroll
        for (int q = 0; q < 4; q++) ob[nt][q] = 0.f;
    float mst[2], lst[2];
    mst[0] = mst[1] = -1e30f;
    lst[0] = lst[1] = 0.f;   // per-lane partial row sums

    uint32_t kbase = sb + (AK_E + lrow * AST + lcol8) * 2;
    uint32_t vbase = sb + (AV_E + lrow_t * AST + dsel) * 2;
    uint32_t soff = 0;
    int sidx = 0;
    int wstage = 2;

    constexpr int NT = S / 64;
    for (int t = 0; t < NT; t++) {
        if (t + 1 < NT) cp_wait<1>(); else cp_wait<0>();
        __syncthreads();
        if (t + 2 < NT) issueKV((t + 2) * 64, wstage);

        // ---- S = Q K^T (already log2-domain: Q pre-scaled) ----
        float sc[8][4];
#pragma unroll
        for (int nt = 0; nt < 8; nt++)
#pragma unroll
            for (int q = 0; q < 4; q++) sc[nt][q] = 0.f;

        const uint32_t kb = kbase + soff;
#pragma unroll
        for (int k = 0; k < 4; k++) {
            uint32_t bfr[8][2];
#pragma unroll
            for (int np = 0; np < 4; np++) {
                uint32_t b0, b1, b2, b3;
                ldsm4(b0, b1, b2, b3, kb + (np * 16 * AST + k * 16) * 2);
                bfr[np * 2 + 0][0] = b0; bfr[np * 2 + 1][0] = b1;
                bfr[np * 2 + 0][1] = b2; bfr[np * 2 + 1][1] = b3;
            }
#pragma unroll
            for (int nt = 0; nt < 8; nt++)
                mma16(sc[nt], aq[k], bfr[nt][0], bfr[nt][1]);
        }

        // ---- mask: warp-uniform all-ones fast path ----
        const int* mstg = ms + sidx * 64;
        const int okk = mstg[lane * 2] & mstg[lane * 2 + 1];
        if (!__all_sync(0xffffffffu, okk != 0)) {
#pragma unroll
            for (int nt = 0; nt < 8; nt++) {
                const int c0 = nt * 8 + cc * 2;
                const float m0v = mstg[c0] ? 0.f : mneg2;
                const float m1v = mstg[c0 + 1] ? 0.f : mneg2;
                sc[nt][0] += m0v; sc[nt][2] += m0v;
                sc[nt][1] += m1v; sc[nt][3] += m1v;
            }
        }

        // ---- row maxes for both halves, ONE packed shuffle phase ----
        float rm[2];
#pragma unroll
        for (int hf = 0; hf < 2; hf++) {
            float r = fmaxf(sc[0][hf * 2 + 0], sc[0][hf * 2 + 1]);
#pragma unroll
            for (int nt = 1; nt < 8; nt++)
                r = fmaxf(r, fmaxf(sc[nt][hf * 2 + 0], sc[nt][hf * 2 + 1]));
            rm[hf] = r;
        }
        {
            uint32_t pm = packbf(rm[0], rm[1]);
            pm = hmax2u(pm, __shfl_xor_sync(0xffffffffu, pm, 1));
            pm = hmax2u(pm, __shfl_xor_sync(0xffffffffu, pm, 2));
            __nv_bfloat162 bm = *(__nv_bfloat162*)&pm;
            rm[0] = __low2float(bm);    // bf16-quantized max: softmax-invariant
            rm[1] = __high2float(bm);
        }

        // ---- online softmax (log2 domain), lane-partial sums ----
#pragma unroll
        for (int hf = 0; hf < 2; hf++) {
            const float mnew = fmaxf(mst[hf], rm[hf]);
            float rs = 0.f;
#pragma unroll
            for (int nt = 0; nt < 8; nt++) {
                float p0 = exp2f(sc[nt][hf * 2 + 0] - mnew);
                float p1 = exp2f(sc[nt][hf * 2 + 1] - mnew);
                sc[nt][hf * 2 + 0] = p0;
                sc[nt][hf * 2 + 1] = p1;
                rs += p0 + p1;
            }
            const bool noup = (mnew == mst[hf]);
            if (__all_sync(0xffffffffu, noup)) {
                lst[hf] += rs;               // cf == 1 warp-wide: skip rescale
            } else {
                const float cf = exp2f(mst[hf] - mnew);
                mst[hf] = mnew;
                lst[hf] = lst[hf] * cf + rs;
#pragma unroll
                for (int nt = 0; nt < 8; nt++) {
                    ob[nt][hf * 2 + 0] *= cf;
                    ob[nt][hf * 2 + 1] *= cf;
                }
            }
        }

        // ---- O += P V, P direct from registers ----
        const uint32_t vb = vbase + soff;
#pragma unroll
        for (int kc = 0; kc < 4; kc++) {
            uint32_t a[4], bfr[8][2];
            a[0] = packbf(sc[2 * kc][0], sc[2 * kc][1]);
            a[1] = packbf(sc[2 * kc][2], sc[2 * kc][3]);
            a[2] = packbf(sc[2 * kc + 1][0], sc[2 * kc + 1][1]);
            a[3] = packbf(sc[2 * kc + 1][2], sc[2 * kc + 1][3]);
#pragma unroll
            for (int np = 0; np < 4; np++) {
                uint32_t b0, b1, b2, b3;
                ldsm4t(b0, b1, b2, b3, vb + (kc * 16 * AST + np * 16) * 2);
                bfr[np * 2 + 0][0] = b0; bfr[np * 2 + 1][0] = b1;
                bfr[np * 2 + 0][1] = b2; bfr[np * 2 + 1][1] = b3;
            }
#pragma unroll
            for (int nt = 0; nt < 8; nt++)
                mma16(ob[nt], a, bfr[nt][0], bfr[nt][1]);
        }

        soff += SROT; if (soff == 3 * SROT) soff = 0;
        sidx = (sidx == 2) ? 0 : sidx + 1;
        wstage = (wstage == 2) ? 0 : wstage + 1;
    }

    // epilogue: reduce lane-partial sums, then O = ob / l
#pragma unroll
    for (int hf = 0; hf < 2; hf++) {
        float lt = lst[hf];
        lt += __shfl_xor_sync(0xffffffffu, lt, 1);
        lt += __shfl_xor_sync(0xffffffffu, lt, 2);
        const float inv = 1.0f / lt;
        const int row = q0 + qb + g + hf * 8;
#pragma unroll
        for (int nt = 0; nt < 8; nt++) {
            const int col = h * HD + nt * 8 + cc * 2;
            *(uint32_t*)(O + (size_t)(b * S + row) * D + col) =
                packbf(ob[nt][hf * 2 + 0] * inv, ob[nt][hf * 2 + 1] * inv);
        }
    }
}

// ---------------- LayerNorm: warp per row, shuffle reduce --------------------
__global__ __launch_bounds__(256) void ln_kernel(
    const float* __restrict__ Y, const float* __restrict__ gamma,
    const float* __restrict__ beta, float* __restrict__ out)
{
    const int lane = threadIdx.x & 31, wid = threadIdx.x >> 5;
    const int row = blockIdx.x * 8 + wid;
    const float* y = Y + (size_t)row * D;

    float s = 0.f, s2 = 0.f;
    float4 v[8];
#pragma unroll
    for (int i = 0; i < 8; i++) {
        v[i] = *(const float4*)(y + lane * 4 + i * 128);
        s += v[i].x + v[i].y + v[i].z + v[i].w;
        s2 = fmaf(v[i].x, v[i].x, s2);
        s2 = fmaf(v[i].y, v[i].y, s2);
        s2 = fmaf(v[i].z, v[i].z, s2);
        s2 = fmaf(v[i].w, v[i].w, s2);
    }
#pragma unroll
    for (int o = 16; o > 0; o >>= 1) {
        s  += __shfl_xor_sync(0xffffffffu, s, o);
        s2 += __shfl_xor_sync(0xffffffffu, s2, o);
    }
    const float mu = s * (1.0f / D);
    const float var = s2 * (1.0f / D) - mu * mu;
    const float inv = rsqrtf(var + 1e-5f);

    float* o = out + (size_t)row * D;
#pragma unroll
    for (int i = 0; i < 8; i++) {
        const int c = lane * 4 + i * 128;
        float4 gv = *(const float4*)(gamma + c);
        float4 bv = *(const float4*)(beta + c);
        float4 r;
        r.x = (v[i].x - mu) * inv * gv.x + bv.x;
        r.y = (v[i].y - mu) * inv * gv.y + bv.y;
        r.z = (v[i].z - mu) * inv * gv.z + bv.z;
        r.w = (v[i].w - mu) * inv * gv.w + bv.w;
        *(float4*)(o + c) = r;
    }
}

// ---------------- launch ------------------------------------------------------
extern "C" void kernel_launch(void* const* d_in, const int* in_sizes, int n_in,
                              void* d_out, int out_size)
{
    const float* x     = (const float*)d_in[0];
    const int*   mask  = (const int*)d_in[1];
    const float* Wq    = (const float*)d_in[2];
    const float* bq    = (const float*)d_in[3];
    const float* Wk    = (const float*)d_in[4];
    const float* bk    = (const float*)d_in[5];
    const float* Wv    = (const float*)d_in[6];
    const float* bv    = (const float*)d_in[7];
    const float* Wo    = (const float*)d_in[8];
    const float* bo    = (const float*)d_in[9];
    const float* gamma = (const float*)d_in[10];
    const float* beta  = (const float*)d_in[11];

    __nv_bfloat16 *Xb, *Wb, *Qb, *Kb, *Vb, *Cb;
    float* Yp;
    cudaGetSymbolAddress((void**)&Xb, g_Xb);
    cudaGetSymbolAddress((void**)&Wb, g_Wb);
    cudaGetSymbolAddress((void**)&Qb, g_Qb);
    cudaGetSymbolAddress((void**)&Kb, g_Kb);
    cudaGetSymbolAddress((void**)&Vb, g_Vb);
    cudaGetSymbolAddress((void**)&Cb, g_Cb);
    cudaGetSymbolAddress((void**)&Yp, g_Y);

    cudaFuncSetAttribute(qkv_gemm,
                         cudaFuncAttributeMaxDynamicSharedMemorySize, GEMM_SMEM);
    cudaFuncSetAttribute(out_gemm,
                         cudaFuncAttributeMaxDynamicSharedMemorySize, GEMM_SMEM);
    cudaFuncSetAttribute(attn_mma,
                         cudaFuncAttributeMaxDynamicSharedMemorySize, ATT_SMEM);

    const int nX4 = NR * D / 4, nW4 = D * D / 4;
    cvt_bf16<<<nX4 / 256, 256>>>(x, Xb, nX4);
    WPtrs ws;
    ws.w[0] = Wq; ws.w[1] = Wk; ws.w[2] = Wv; ws.w[3] = Wo;
    cvt_w4<<<dim3(nW4 / 256, 4), 256>>>(ws, Wb);

    QKVOut io;
    io.out[0] = Qb; io.out[1] = Kb; io.out[2] = Vb;
    io.bias[0] = bq; io.bias[1] = bk; io.bias[2] = bv;
    io.oscale[0] = 0.125f * 1.44269504f;   // fold softmax scale+log2e into Q
    io.oscale[1] = 1.0f;
    io.oscale[2] = 1.0f;
    qkv_gemm<<<dim3(24, NR / 128), 128, GEMM_SMEM>>>(Xb, Wb, io);

    attn_mma<<<dim3(S / 128, H, B), 256, ATT_SMEM>>>(Qb, Kb, Vb, mask, Cb);

    out_gemm<<<dim3(8, NR / 128), 128, GEMM_SMEM>>>(
        Cb, Wb + (size_t)3 * D * D, bo, x, Yp);
    ln_kernel<<<NR / 8, 256>>>(Yp, gamma, beta, (float*)d_out);
}

// round 16
// speedup vs baseline: 1.6663x; 1.6663x over previous
#include <cuda_runtime.h>
#include <cuda_bf16.h>
#include <cstdint>
#include <math.h>

constexpr int B = 4, S = 2048, D = 1024, H = 16, HD = 64;
constexpr int NR = B * S;  // 8192 rows

// ---------------- scratch (static device globals; no allocation) -------------
__device__ __nv_bfloat16 g_Xb[(size_t)NR * D];      // x bf16
__device__ __nv_bfloat16 g_Wb[(size_t)4 * D * D];   // Wq,Wk,Wv,Wo bf16
__device__ __nv_bfloat16 g_Qb[(size_t)NR * D];      // pre-scaled by 0.125*log2e
__device__ __nv_bfloat16 g_Kb[(size_t)NR * D];
__device__ __nv_bfloat16 g_Vb[(size_t)NR * D];
__device__ __nv_bfloat16 g_Cb[(size_t)NR * D];      // attention out bf16
__device__ float         g_Y[(size_t)NR * D];

// ======================= helpers ============================================
__device__ __forceinline__ uint32_t smem_u32(const void* p) {
    uint32_t a;
    asm("{ .reg .u64 t; cvta.to.shared.u64 t, %1; cvt.u32.u64 %0, t; }"
        : "=r"(a) : "l"(p));
    return a;
}
__device__ __forceinline__ void ldsm4(uint32_t& r0, uint32_t& r1, uint32_t& r2,
                                      uint32_t& r3, uint32_t addr) {
    asm volatile("ldmatrix.sync.aligned.m8n8.x4.shared.b16 {%0,%1,%2,%3}, [%4];"
                 : "=r"(r0), "=r"(r1), "=r"(r2), "=r"(r3) : "r"(addr));
}
__device__ __forceinline__ void ldsm4t(uint32_t& r0, uint32_t& r1, uint32_t& r2,
                                       uint32_t& r3, uint32_t addr) {
    asm volatile("ldmatrix.sync.aligned.m8n8.x4.trans.shared.b16 {%0,%1,%2,%3}, [%4];"
                 : "=r"(r0), "=r"(r1), "=r"(r2), "=r"(r3) : "r"(addr));
}
__device__ __forceinline__ void mma16(float (&c)[4], const uint32_t (&a)[4],
                                      uint32_t b0, uint32_t b1) {
    asm volatile(
        "mma.sync.aligned.m16n8k16.row.col.f32.bf16.bf16.f32 "
        "{%0,%1,%2,%3}, {%4,%5,%6,%7}, {%8,%9}, {%0,%1,%2,%3};"
        : "+f"(c[0]), "+f"(c[1]), "+f"(c[2]), "+f"(c[3])
        : "r"(a[0]), "r"(a[1]), "r"(a[2]), "r"(a[3]), "r"(b0), "r"(b1));
}
__device__ __forceinline__ void cp_async16(uint32_t s, const void* g) {
    asm volatile("cp.async.cg.shared.global [%0], [%1], 16;" :: "r"(s), "l"(g));
}
__device__ __forceinline__ void cp_commit() {
    asm volatile("cp.async.commit_group;" ::: "memory");
}
template <int N>
__device__ __forceinline__ void cp_wait() {
    asm volatile("cp.async.wait_group %0;" :: "n"(N) : "memory");
}
__device__ __forceinline__ uint32_t packbf(float x, float y) {
    __nv_bfloat162 p = __floats2bfloat162_rn(x, y);
    return *(uint32_t*)&p;
}
__device__ __forceinline__ uint32_t hmax2u(uint32_t a, uint32_t b) {
    __nv_bfloat162 x = *(__nv_bfloat162*)&a;
    __nv_bfloat162 y = *(__nv_bfloat162*)&b;
    __nv_bfloat162 r = __hmax2(x, y);
    return *(uint32_t*)&r;
}

// ======================= fp32 -> bf16 prep ===================================
__global__ __launch_bounds__(256) void cvt_bf16(const float* __restrict__ in,
                                                __nv_bfloat16* __restrict__ out,
                                                int n4)
{
    const int i = (blockIdx.x * 256 + threadIdx.x) * 4;
    if (i < n4 * 4) {
        float4 v = *(const float4*)(in + i);
        uint2 u;
        u.x = packbf(v.x, v.y);
        u.y = packbf(v.z, v.w);
        *(uint2*)(out + i) = u;
    }
}

struct WPtrs { const float* w[4]; };

__global__ __launch_bounds__(256) void cvt_w4(WPtrs ws,
                                              __nv_bfloat16* __restrict__ out)
{
    const int i = (blockIdx.x * 256 + threadIdx.x) * 4;
    const float* in = ws.w[blockIdx.y];
    __nv_bfloat16* o = out + (size_t)blockIdx.y * D * D;
    float4 v = *(const float4*)(in + i);
    uint2 u;
    u.x = packbf(v.x, v.y);
    u.y = packbf(v.z, v.w);
    *(uint2*)(o + i) = u;
}

// ======================= bf16 mma GEMM core (BK=64, 3 CTAs/SM) ==============
// Single barrier per chunk: wait(c) -> bar -> issue(c+1) -> compute(c).
constexpr int GST = 72;                 // smem row stride (bf16 elems)
constexpr int G_STAGE = 256 * GST;      // bf16 elems per stage
constexpr int GEMM_SMEM = 2 * G_STAGE * 2;  // 73728 B

struct QKVOut {
    __nv_bfloat16* out[3];
    const float* bias[3];
    float oscale[3];
};

template <typename AccFn>
__device__ __forceinline__ void gemm_body(
    const __nv_bfloat16* __restrict__ A, const __nv_bfloat16* __restrict__ W,
    int n0, int m0, __nv_bfloat16* gsm, AccFn&& emit)
{
    const int tid = threadIdx.x;
    const int lane = tid & 31, wid = tid >> 5;   // 4 warps
    const int wr = wid >> 1, wc = wid & 1;        // 2x2 warp grid, 64x64 each
    const int lrow = lane & 15;
    const int lcol8 = (lane >> 4) * 8;
    const uint32_t sbase = smem_u32(gsm);

    float acc[4][8][4];
#pragma unroll
    for (int mt = 0; mt < 4; mt++)
#pragma unroll
        for (int nt = 0; nt < 8; nt++)
#pragma unroll
            for (int q = 0; q < 4; q++) acc[mt][nt][q] = 0.f;

    auto issue_chunk = [&](int c) {
        const int k0 = c * 64;
        const uint32_t stb = sbase + (c & 1) * G_STAGE * 2;
#pragma unroll
        for (int i = 0; i < 16; i++) {
            const int idx = tid + i * 128;
            const int t = idx & 1023;
            const int row = t >> 3, c8 = (t & 7) * 8;
            const __nv_bfloat16* g =
                (idx < 1024 ? A + (size_t)(n0 + row) * D
                            : W + (size_t)(m0 + row) * D) + k0 + c8;
            const int srow = row + (idx < 1024 ? 0 : 128);
            cp_async16(stb + (srow * GST + c8) * 2, g);
        }
        cp_commit();
    };

    issue_chunk(0);
    for (int c = 0; c < 16; c++) {
        cp_wait<0>();          // chunk c arrived (only group outstanding)
        __syncthreads();       // data visible + compute(c-1) done block-wide
        if (c + 1 < 16) issue_chunk(c + 1);  // writes stage of chunk c-1

        const uint32_t stb = sbase + (c & 1) * G_STAGE * 2;
#pragma unroll
        for (int k = 0; k < 4; k++) {
            uint32_t a[4][4];
            uint32_t bfr[8][2];
#pragma unroll
            for (int mt = 0; mt < 4; mt++) {
                const uint32_t addr =
                    stb + ((wr * 64 + mt * 16 + lrow) * GST + k * 16 + lcol8) * 2;
                ldsm4(a[mt][0], a[mt][1], a[mt][2], a[mt][3], addr);
            }
#pragma unroll
            for (int np = 0; np < 4; np++) {
                const uint32_t addr =
                    stb + ((128 + wc * 64 + np * 16 + lrow) * GST + k * 16 + lcol8) * 2;
                uint32_t b0, b1, b2, b3;
                ldsm4(b0, b1, b2, b3, addr);
                bfr[np * 2 + 0][0] = b0; bfr[np * 2 + 1][0] = b1;
                bfr[np * 2 + 0][1] = b2; bfr[np * 2 + 1][1] = b3;
            }
#pragma unroll
            for (int mt = 0; mt < 4; mt++)
#pragma unroll
                for (int nt = 0; nt < 8; nt++)
                    mma16(acc[mt][nt], a[mt], bfr[nt][0], bfr[nt][1]);
        }
    }

    const int g = lane >> 2, cc = lane & 3;
#pragma unroll
    for (int mt = 0; mt < 4; mt++)
#pragma unroll
        for (int hf = 0; hf < 2; hf++) {
            const int row = n0 + wr * 64 + mt * 16 + g + hf * 8;
#pragma unroll
            for (int nt = 0; nt < 8; nt++) {
                const int col = m0 + wc * 64 + nt * 8 + cc * 2;
                emit(row, col, acc[mt][nt][hf * 2 + 0], acc[mt][nt][hf * 2 + 1]);
            }
        }
}

// Fused QKV projection: grid.x in [0,24): sel = x>>3, m-block = x&7.
__global__ __launch_bounds__(128, 3) void qkv_gemm(
    const __nv_bfloat16* __restrict__ A, const __nv_bfloat16* __restrict__ Wall,
    QKVOut io)
{
    extern __shared__ __nv_bfloat16 gsm[];
    const int sel = blockIdx.x >> 3;
    const int m0 = (blockIdx.x & 7) * 128;
    const int n0 = blockIdx.y * 128;
    const __nv_bfloat16* W = Wall + (size_t)sel * D * D;
    __nv_bfloat16* out = io.out[sel];
    const float* bias = io.bias[sel];
    const float os = io.oscale[sel];

    gemm_body(A, W, n0, m0, gsm,
              [&](int row, int col, float vx, float vy) {
                  float2 bv = *(const float2*)(bias + col);
                  *(uint32_t*)(out + (size_t)row * D + col) =
                      packbf((vx + bv.x) * os, (vy + bv.y) * os);
              });
}

// Output projection with residual, fp32 out.
__global__ __launch_bounds__(128, 3) void out_gemm(
    const __nv_bfloat16* __restrict__ A, const __nv_bfloat16* __restrict__ W,
    const float* __restrict__ bias, const float* __restrict__ R,
    float* __restrict__ C)
{
    extern __shared__ __nv_bfloat16 gsm[];
    const int m0 = blockIdx.x * 128;
    const int n0 = blockIdx.y * 128;

    gemm_body(A, W, n0, m0, gsm,
              [&](int row, int col, float vx, float vy) {
                  float2 bv = *(const float2*)(bias + col);
                  float2 rv = *(const float2*)(R + (size_t)row * D + col);
                  float2 o;
                  o.x = vx + bv.x + rv.x;
                  o.y = vy + bv.y + rv.y;
                  *(float2*)(C + (size_t)row * D + col) = o;
              });
}

// ======================= bf16 mma flash attention ===========================
// Block: 128 q rows, 8 warps x 16 rows, 256 threads, 2 CTAs/SM. (R14 config)
constexpr int AST = 72;
constexpr int AQ_E = 0;
constexpr int AK_E = 128 * AST;
constexpr int AV_E = AK_E + 3 * 64 * AST;
constexpr int AEND_E = AV_E + 3 * 64 * AST;
constexpr int AM_BYTE = AEND_E * 2;
constexpr int ATT_SMEM = AM_BYTE + 3 * 64 * 4;  // ~74.5 KB
constexpr int KSTG = 64 * AST;
constexpr uint32_t SROT = KSTG * 2;

__global__ __launch_bounds__(256, 2) void attn_mma(
    const __nv_bfloat16* __restrict__ Q, const __nv_bfloat16* __restrict__ K,
    const __nv_bfloat16* __restrict__ V, const int* __restrict__ mask,
    __nv_bfloat16* __restrict__ O)
{
    extern __shared__ __nv_bfloat16 smb[];
    int* ms = (int*)((char*)smb + AM_BYTE);
    const int tid = threadIdx.x, lane = tid & 31, wid = tid >> 5;
    const int b = blockIdx.z, h = blockIdx.y, q0 = blockIdx.x * 128;
    const uint32_t sb = smem_u32(smb);
    const int lrow = lane & 15;
    const int lcol8 = (lane >> 4) * 8;
    const int lrow_t = (lane & 7) + ((lane >> 4) << 3);
    const int dsel = ((lane >> 3) & 1) * 8;
    const int g = lane >> 2, cc = lane & 3;
    const int qb = wid * 16;
    const float mneg2 = -1.44269504e9f;   // -1e9 * log2(e)

    // Q tile (128 x 64 bf16) via cp.async — first commit group
#pragma unroll
    for (int i = 0; i < 4; i++) {
        const int idx = tid + i * 256;
        const int row = idx >> 3, c8 = (idx & 7) * 8;
        cp_async16(sb + (AQ_E + row * AST + c8) * 2,
                   Q + (size_t)(b * S + q0 + row) * D + h * HD + c8);
    }
    cp_commit();

    auto issueKV = [&](int k0, int stage) {
#pragma unroll
        for (int j = 0; j < 2; j++) {
            const int idx = tid + j * 256;
            const int row = idx >> 3, c8 = (idx & 7) * 8;
            cp_async16(sb + ((AK_E + stage * KSTG) + row * AST + c8) * 2,
                       K + (size_t)(b * S + k0 + row) * D + h * HD + c8);
            cp_async16(sb + ((AV_E + stage * KSTG) + row * AST + c8) * 2,
                       V + (size_t)(b * S + k0 + row) * D + h * HD + c8);
        }
        if (tid < 16)
            cp_async16(sb + AM_BYTE + stage * 256 + tid * 16,
                       mask + b * S + k0 + tid * 4);
        cp_commit();
    };

    issueKV(0, 0);
    issueKV(64, 1);

    // Hoist Q fragments
    cp_wait<2>();
    __syncthreads();
    uint32_t aq[4][4];
#pragma unroll
    for (int k = 0; k < 4; k++) {
        const uint32_t addr =
            sb + ((AQ_E + (qb + lrow) * AST) + k * 16 + lcol8) * 2;
        ldsm4(aq[k][0], aq[k][1], aq[k][2], aq[k][3], addr);
    }

    float ob[8][4];
#pragma unroll
    for (int nt = 0; nt < 8; nt++)
#pragma unroll
        for (int q = 0; q < 4; q++) ob[nt][q] = 0.f;
    float mst[2], lst[2];
    mst[0] = mst[1] = -1e30f;
    lst[0] = lst[1] = 0.f;   // per-lane partial row sums

    uint32_t kbase = sb + (AK_E + lrow * AST + lcol8) * 2;
    uint32_t vbase = sb + (AV_E + lrow_t * AST + dsel) * 2;
    uint32_t soff = 0;
    int sidx = 0;
    int wstage = 2;

    constexpr int NT = S / 64;
    for (int t = 0; t < NT; t++) {
        if (t + 1 < NT) cp_wait<1>(); else cp_wait<0>();
        __syncthreads();
        if (t + 2 < NT) issueKV((t + 2) * 64, wstage);

        // ---- S = Q K^T (already log2-domain: Q pre-scaled) ----
        float sc[8][4];
#pragma unroll
        for (int nt = 0; nt < 8; nt++)
#pragma unroll
            for (int q = 0; q < 4; q++) sc[nt][q] = 0.f;

        const uint32_t kb = kbase + soff;
#pragma unroll
        for (int k = 0; k < 4; k++) {
            uint32_t bfr[8][2];
#pragma unroll
            for (int np = 0; np < 4; np++) {
                uint32_t b0, b1, b2, b3;
                ldsm4(b0, b1, b2, b3, kb + (np * 16 * AST + k * 16) * 2);
                bfr[np * 2 + 0][0] = b0; bfr[np * 2 + 1][0] = b1;
                bfr[np * 2 + 0][1] = b2; bfr[np * 2 + 1][1] = b3;
            }
#pragma unroll
            for (int nt = 0; nt < 8; nt++)
                mma16(sc[nt], aq[k], bfr[nt][0], bfr[nt][1]);
        }

        // ---- mask: warp-uniform all-ones fast path ----
        const int* mstg = ms + sidx * 64;
        const int okk = mstg[lane * 2] & mstg[lane * 2 + 1];
        if (!__all_sync(0xffffffffu, okk != 0)) {
#pragma unroll
            for (int nt = 0; nt < 8; nt++) {
                const int c0 = nt * 8 + cc * 2;
                const float m0v = mstg[c0] ? 0.f : mneg2;
                const float m1v = mstg[c0 + 1] ? 0.f : mneg2;
                sc[nt][0] += m0v; sc[nt][2] += m0v;
                sc[nt][1] += m1v; sc[nt][3] += m1v;
            }
        }

        // ---- row maxes for both halves, ONE packed shuffle phase ----
        float rm[2];
#pragma unroll
        for (int hf = 0; hf < 2; hf++) {
            float r = fmaxf(sc[0][hf * 2 + 0], sc[0][hf * 2 + 1]);
#pragma unroll
            for (int nt = 1; nt < 8; nt++)
                r = fmaxf(r, fmaxf(sc[nt][hf * 2 + 0], sc[nt][hf * 2 + 1]));
            rm[hf] = r;
        }
        {
            uint32_t pm = packbf(rm[0], rm[1]);
            pm = hmax2u(pm, __shfl_xor_sync(0xffffffffu, pm, 1));
            pm = hmax2u(pm, __shfl_xor_sync(0xffffffffu, pm, 2));
            __nv_bfloat162 bm = *(__nv_bfloat162*)&pm;
            rm[0] = __low2float(bm);    // bf16-quantized max: softmax-invariant
            rm[1] = __high2float(bm);
        }

        // ---- online softmax (log2 domain), lane-partial sums ----
#pragma unroll
        for (int hf = 0; hf < 2; hf++) {
            const float mnew = fmaxf(mst[hf], rm[hf]);
            float rs = 0.f;
#pragma unroll
            for (int nt = 0; nt < 8; nt++) {
                float p0 = exp2f(sc[nt][hf * 2 + 0] - mnew);
                float p1 = exp2f(sc[nt][hf * 2 + 1] - mnew);
                sc[nt][hf * 2 + 0] = p0;
                sc[nt][hf * 2 + 1] = p1;
                rs += p0 + p1;
            }
            const bool noup = (mnew == mst[hf]);
            if (__all_sync(0xffffffffu, noup)) {
                lst[hf] += rs;               // cf == 1 warp-wide: skip rescale
            } else {
                const float cf = exp2f(mst[hf] - mnew);
                mst[hf] = mnew;
                lst[hf] = lst[hf] * cf + rs;
#pragma unroll
                for (int nt = 0; nt < 8; nt++) {
                    ob[nt][hf * 2 + 0] *= cf;
                    ob[nt][hf * 2 + 1] *= cf;
                }
            }
        }

        // ---- O += P V, P direct from registers ----
        const uint32_t vb = vbase + soff;
#pragma unroll
        for (int kc = 0; kc < 4; kc++) {
            uint32_t a[4], bfr[8][2];
            a[0] = packbf(sc[2 * kc][0], sc[2 * kc][1]);
            a[1] = packbf(sc[2 * kc][2], sc[2 * kc][3]);
            a[2] = packbf(sc[2 * kc + 1][0], sc[2 * kc + 1][1]);
            a[3] = packbf(sc[2 * kc + 1][2], sc[2 * kc + 1][3]);
#pragma unroll
            for (int np = 0; np < 4; np++) {
                uint32_t b0, b1, b2, b3;
                ldsm4t(b0, b1, b2, b3, vb + (kc * 16 * AST + np * 16) * 2);
                bfr[np * 2 + 0][0] = b0; bfr[np * 2 + 1][0] = b1;
                bfr[np * 2 + 0][1] = b2; bfr[np * 2 + 1][1] = b3;
            }
#pragma unroll
            for (int nt = 0; nt < 8; nt++)
                mma16(ob[nt], a, bfr[nt][0], bfr[nt][1]);
        }

        soff += SROT; if (soff == 3 * SROT) soff = 0;
        sidx = (sidx == 2) ? 0 : sidx + 1;
        wstage = (wstage == 2) ? 0 : wstage + 1;
    }

    // epilogue: reduce lane-partial sums, then O = ob / l
#pragma unroll
    for (int hf = 0; hf < 2; hf++) {
        float lt = lst[hf];
        lt += __shfl_xor_sync(0xffffffffu, lt, 1);
        lt += __shfl_xor_sync(0xffffffffu, lt, 2);
        const float inv = 1.0f / lt;
        const int row = q0 + qb + g + hf * 8;
#pragma unroll
        for (int nt = 0; nt < 8; nt++) {
            const int col = h * HD + nt * 8 + cc * 2;
            *(uint32_t*)(O + (size_t)(b * S + row) * D + col) =
                packbf(ob[nt][hf * 2 + 0] * inv, ob[nt][hf * 2 + 1] * inv);
        }
    }
}

// ---------------- LayerNorm: warp per row, shuffle reduce --------------------
__global__ __launch_bounds__(256) void ln_kernel(
    const float* __restrict__ Y, const float* __restrict__ gamma,
    const float* __restrict__ beta, float* __restrict__ out)
{
    const int lane = threadIdx.x & 31, wid = threadIdx.x >> 5;
    const int row = blockIdx.x * 8 + wid;
    const float* y = Y + (size_t)row * D;

    float s = 0.f, s2 = 0.f;
    float4 v[8];
#pragma unroll
    for (int i = 0; i < 8; i++) {
        v[i] = *(const float4*)(y + lane * 4 + i * 128);
        s += v[i].x + v[i].y + v[i].z + v[i].w;
        s2 = fmaf(v[i].x, v[i].x, s2);
        s2 = fmaf(v[i].y, v[i].y, s2);
        s2 = fmaf(v[i].z, v[i].z, s2);
        s2 = fmaf(v[i].w, v[i].w, s2);
    }
#pragma unroll
    for (int o = 16; o > 0; o >>= 1) {
        s  += __shfl_xor_sync(0xffffffffu, s, o);
        s2 += __shfl_xor_sync(0xffffffffu, s2, o);
    }
    const float mu = s * (1.0f / D);
    const float var = s2 * (1.0f / D) - mu * mu;
    const float inv = rsqrtf(var + 1e-5f);

    float* o = out + (size_t)row * D;
#pragma unroll
    for (int i = 0; i < 8; i++) {
        const int c = lane * 4 + i * 128;
        float4 gv = *(const float4*)(gamma + c);
        float4 bv = *(const float4*)(beta + c);
        float4 r;
        r.x = (v[i].x - mu) * inv * gv.x + bv.x;
        r.y = (v[i].y - mu) * inv * gv.y + bv.y;
        r.z = (v[i].z - mu) * inv * gv.z + bv.z;
        r.w = (v[i].w - mu) * inv * gv.w + bv.w;
        *(float4*)(o + c) = r;
    }
}

// ---------------- launch ------------------------------------------------------
extern "C" void kernel_launch(void* const* d_in, const int* in_sizes, int n_in,
                              void* d_out, int out_size)
{
    const float* x     = (const float*)d_in[0];
    const int*   mask  = (const int*)d_in[1];
    const float* Wq    = (const float*)d_in[2];
    const float* bq    = (const float*)d_in[3];
    const float* Wk    = (const float*)d_in[4];
    const float* bk    = (const float*)d_in[5];
    const float* Wv    = (const float*)d_in[6];
    const float* bv    = (const float*)d_in[7];
    const float* Wo    = (const float*)d_in[8];
    const float* bo    = (const float*)d_in[9];
    const float* gamma = (const float*)d_in[10];
    const float* beta  = (const float*)d_in[11];

    __nv_bfloat16 *Xb, *Wb, *Qb, *Kb, *Vb, *Cb;
    float* Yp;
    cudaGetSymbolAddress((void**)&Xb, g_Xb);
    cudaGetSymbolAddress((void**)&Wb, g_Wb);
    cudaGetSymbolAddress((void**)&Qb, g_Qb);
    cudaGetSymbolAddress((void**)&Kb, g_Kb);
    cudaGetSymbolAddress((void**)&Vb, g_Vb);
    cudaGetSymbolAddress((void**)&Cb, g_Cb);
    cudaGetSymbolAddress((void**)&Yp, g_Y);

    cudaFuncSetAttribute(qkv_gemm,
                         cudaFuncAttributeMaxDynamicSharedMemorySize, GEMM_SMEM);
    cudaFuncSetAttribute(out_gemm,
                         cudaFuncAttributeMaxDynamicSharedMemorySize, GEMM_SMEM);
    cudaFuncSetAttribute(attn_mma,
                         cudaFuncAttributeMaxDynamicSharedMemorySize, ATT_SMEM);

    const int nX4 = NR * D / 4, nW4 = D * D / 4;
    cvt_bf16<<<nX4 / 256, 256>>>(x, Xb, nX4);
    WPtrs ws;
    ws.w[0] = Wq; ws.w[1] = Wk; ws.w[2] = Wv; ws.w[3] = Wo;
    cvt_w4<<<dim3(nW4 / 256, 4), 256>>>(ws, Wb);

    QKVOut io;
    io.out[0] = Qb; io.out[1] = Kb; io.out[2] = Vb;
    io.bias[0] = bq; io.bias[1] = bk; io.bias[2] = bv;
    io.oscale[0] = 0.125f * 1.44269504f;   // fold softmax scale+log2e into Q
    io.oscale[1] = 1.0f;
    io.oscale[2] = 1.0f;
    qkv_gemm<<<dim3(24, NR / 128), 128, GEMM_SMEM>>>(Xb, Wb, io);

    attn_mma<<<dim3(S / 128, H, B), 256, ATT_SMEM>>>(Qb, Kb, Vb, mask, Cb);

    out_gemm<<<dim3(8, NR / 128), 128, GEMM_SMEM>>>(
        Cb, Wb + (size_t)3 * D * D, bo, x, Yp);
    ln_kernel<<<NR / 8, 256>>>(Yp, gamma, beta, (float*)d_out);
}